// round 4
// baseline (speedup 1.0000x reference)
#include <cuda_runtime.h>
#include <cuda_bf16.h>
#include <cstdint>
#include <cfloat>

#define B_  16384
#define TD_ 4096
#define L_  1024
#define K_  8192
#define O_  128

#define MARGIN 1.5e-3f

// ---------------- scratch (device globals) -----------------------------------
__device__ float  g_ze[(size_t)B_ * L_];            // 64 MB
__device__ __nv_bfloat16 g_zeb[(size_t)B_ * L_];    // 32 MB
__device__ __nv_bfloat16 g_cbb[(size_t)K_ * L_];    // 16 MB
__device__ __nv_bfloat16 g_qb[(size_t)B_ * L_];     // 32 MB (gathered codebook rows)
__device__ __nv_bfloat16 g_wclsb[(size_t)O_ * L_];
__device__ float  g_P[B_];
__device__ float  g_c[K_];
__device__ int    g_idx[B_];
__device__ uint32_t g_cand_col[(size_t)B_ * 32];
__device__ float    g_cand_d[(size_t)B_ * 32];
__device__ double g_rowloss[B_];

// ---------------- mma.sync helper (m16n8k16 bf16, fp32 accum) ----------------
__device__ __forceinline__ void mma16816(float* c, uint32_t a0, uint32_t a1,
                                         uint32_t a2, uint32_t a3,
                                         uint32_t b0, uint32_t b1) {
    asm volatile(
        "mma.sync.aligned.m16n8k16.row.col.f32.bf16.bf16.f32 "
        "{%0,%1,%2,%3}, {%4,%5,%6,%7}, {%8,%9}, {%0,%1,%2,%3};"
        : "+f"(c[0]), "+f"(c[1]), "+f"(c[2]), "+f"(c[3])
        : "r"(a0), "r"(a1), "r"(a2), "r"(a3), "r"(b0), "r"(b1));
}

// smem tile: 128 rows x 64 bf16, padded to 72 bf16 (144B) per row.
#define TROW 144
#define TSZ  (128 * TROW)      // 18432 B per stage
// dyn smem layout: A0@0 A1@TSZ B0@2*TSZ B1@3*TSZ sc@4*TSZ
#define SM_DYN (4 * TSZ + 512)

// load a 128x64 bf16 chunk into a padded smem stage (256 threads)
__device__ __forceinline__ void load_tile(char* dst, const __nv_bfloat16* src,
                                          int row0, int kc, int tid) {
    int r = tid >> 1, seg = tid & 1;
    const uint4* s = (const uint4*)(src + (size_t)(row0 + r) * L_ + kc + seg * 32);
    uint4* d = (uint4*)(dst + r * TROW + seg * 64);
    d[0] = s[0]; d[1] = s[1]; d[2] = s[2]; d[3] = s[3];
}

// one 64-wide K-chunk of mma work on a stage pair
__device__ __forceinline__ void mma_chunk(const char* smA, const char* smB,
                                          int wm, int wn, int g, int tig,
                                          float acc[2][8][4]) {
    #pragma unroll
    for (int kk = 0; kk < 4; kk++) {
        uint32_t a[2][4];
        #pragma unroll
        for (int m2 = 0; m2 < 2; m2++) {
            int r0 = wm * 32 + m2 * 16 + g;
            int cb0 = (kk * 16 + 2 * tig) * 2;
            a[m2][0] = *(const uint32_t*)(smA + r0 * TROW + cb0);
            a[m2][1] = *(const uint32_t*)(smA + (r0 + 8) * TROW + cb0);
            a[m2][2] = *(const uint32_t*)(smA + r0 * TROW + cb0 + 16);
            a[m2][3] = *(const uint32_t*)(smA + (r0 + 8) * TROW + cb0 + 16);
        }
        #pragma unroll
        for (int n = 0; n < 8; n++) {
            int cn = wn * 64 + n * 8 + g;
            int cb0 = (kk * 16 + 2 * tig) * 2;
            uint32_t b0 = *(const uint32_t*)(smB + cn * TROW + cb0);
            uint32_t b1 = *(const uint32_t*)(smB + cn * TROW + cb0 + 16);
            mma16816(acc[0][n], a[0][0], a[0][1], a[0][2], a[0][3], b0, b1);
            mma16816(acc[1][n], a[1][0], a[1][1], a[1][2], a[1][3], b0, b1);
        }
    }
}

// ================= fused dist GEMM (bf16 HMMA) + candidate collect ===========
__global__ __launch_bounds__(256) void dist_mma_kernel(void)
{
    extern __shared__ char sm[];
    char* A0 = sm;            char* A1 = sm + TSZ;
    char* B0 = sm + 2 * TSZ;  char* B1 = sm + 3 * TSZ;
    float* sc = (float*)(sm + 4 * TSZ);

    int tid = threadIdx.x, w = tid >> 5, lane = tid & 31;
    int wm = w & 3, wn = w >> 2;
    int g = lane >> 2, tig = lane & 3;
    int bm = blockIdx.x * 128;

    float P4[4];
    #pragma unroll
    for (int ri = 0; ri < 4; ri++) P4[ri] = g_P[bm + wm * 32 + ri * 8 + g];

    float bestv[4] = {FLT_MAX, FLT_MAX, FLT_MAX, FLT_MAX};
    int cnt[4] = {0, 0, 0, 0};
    int ovf[4] = {0, 0, 0, 0};
    uint32_t ccol[4][4];
    float    cd[4][4];

    for (int nt = 0; nt < K_ / 128; nt++) {
        int n0 = nt * 128;
        if (tid < 128) sc[tid] = g_c[n0 + tid];

        float acc[2][8][4];
        #pragma unroll
        for (int m2 = 0; m2 < 2; m2++)
            #pragma unroll
            for (int n = 0; n < 8; n++)
                #pragma unroll
                for (int q = 0; q < 4; q++) acc[m2][n][q] = 0.0f;

        load_tile(A0, g_zeb, bm, 0, tid);
        load_tile(B0, g_cbb, n0, 0, tid);
        __syncthreads();
        for (int c = 0; c < 16; c++) {
            if (c + 1 < 16) {
                char* an = (c & 1) ? A0 : A1;
                char* bn2 = (c & 1) ? B0 : B1;
                load_tile(an, g_zeb, bm, (c + 1) * 64, tid);
                load_tile(bn2, g_cbb, n0, (c + 1) * 64, tid);
            }
            mma_chunk((c & 1) ? A1 : A0, (c & 1) ? B1 : B0, wm, wn, g, tig, acc);
            __syncthreads();
        }

        // epilogue: candidates per (thread, row)
        #pragma unroll
        for (int m2 = 0; m2 < 2; m2++) {
            #pragma unroll
            for (int q = 0; q < 4; q++) {
                int ri = m2 * 2 + (q >> 1);
                float P = P4[ri];
                #pragma unroll
                for (int n = 0; n < 8; n++) {
                    int cl = wn * 64 + n * 8 + 2 * tig + (q & 1);
                    float t = P - 2.0f * acc[m2][n][q];
                    float d = t + sc[cl];
                    if (d < bestv[ri] + MARGIN) {
                        if (d < bestv[ri]) bestv[ri] = d;
                        if (cnt[ri] < 4) {
                            ccol[ri][cnt[ri]] = (uint32_t)(n0 + cl);
                            cd[ri][cnt[ri]] = d;
                            cnt[ri]++;
                        } else {
                            int w2 = 0;
                            #pragma unroll
                            for (int e = 0; e < 4; e++)
                                if (cd[ri][e] < bestv[ri] + MARGIN) {
                                    ccol[ri][w2] = ccol[ri][e];
                                    cd[ri][w2] = cd[ri][e];
                                    w2++;
                                }
                            cnt[ri] = w2;
                            if (cnt[ri] < 4) {
                                ccol[ri][cnt[ri]] = (uint32_t)(n0 + cl);
                                cd[ri][cnt[ri]] = d;
                                cnt[ri]++;
                            } else ovf[ri] = 1;
                        }
                    }
                }
            }
        }
        __syncthreads();
    }

    // write candidate slots: per row, slot = tig*2 + wn, 4 entries each
    int slot = tig * 2 + wn;
    #pragma unroll
    for (int ri = 0; ri < 4; ri++) {
        int row = bm + wm * 32 + ri * 8 + g;
        size_t base = (size_t)row * 32 + slot * 4;
        #pragma unroll
        for (int e = 0; e < 4; e++) {
            uint32_t col = (e < cnt[ri]) ? ccol[ri][e] : 0xFFFFFFFFu;
            float dv = (e < cnt[ri]) ? cd[ri][e] : FLT_MAX;
            if (ovf[ri] && e == 3) { col = 0xFFFFFFFEu; dv = FLT_MAX; }
            g_cand_col[base + e] = col;
            g_cand_d[base + e] = dv;
        }
    }
}

// ================= exact refinement (sequential-k fp32 fma chain) ============
__global__ void refine_kernel(const float* __restrict__ cb,
                              float* __restrict__ out_idx_f, int write_idx)
{
    int w = threadIdx.x >> 5, lane = threadIdx.x & 31;
    int row = blockIdx.x * 8 + w;
    const float* ze = g_ze + (size_t)row * L_;
    float P = g_P[row];

    uint32_t ecol = g_cand_col[(size_t)row * 32 + lane];
    float ed = g_cand_d[(size_t)row * 32 + lane];

    int ovf = __any_sync(0xffffffffu, ecol == 0xFFFFFFFEu);

    float bd = FLT_MAX; int bi = 0x7FFFFFFF;
    if (!ovf) {
        float m = ed;
        #pragma unroll
        for (int o = 16; o > 0; o >>= 1)
            m = fminf(m, __shfl_xor_sync(0xffffffffu, m, o));
        if (ecol < 0xFFFFFFFEu && ed < m + MARGIN) {
            const float* e = cb + (size_t)ecol * L_;
            float s = 0.0f;
            #pragma unroll 4
            for (int k = 0; k < L_; k++) s = fmaf(__ldg(&ze[k]), __ldg(&e[k]), s);
            float t = P - 2.0f * s;
            bd = t + __ldg(&g_c[ecol]);
            bi = (int)ecol;
        }
    } else {
        for (int col = lane; col < K_; col += 32) {
            const float* e = cb + (size_t)col * L_;
            float s = 0.0f;
            #pragma unroll 4
            for (int k = 0; k < L_; k++) s = fmaf(__ldg(&ze[k]), __ldg(&e[k]), s);
            float t = P - 2.0f * s;
            float d = t + __ldg(&g_c[col]);
            if (d < bd || (d == bd && col < bi)) { bd = d; bi = col; }
        }
    }
    #pragma unroll
    for (int o = 16; o > 0; o >>= 1) {
        float od = __shfl_xor_sync(0xffffffffu, bd, o);
        int oi = __shfl_xor_sync(0xffffffffu, bi, o);
        if (od < bd || (od == bd && oi < bi)) { bd = od; bi = oi; }
    }
    if (lane == 0) {
        g_idx[row] = bi;
        if (write_idx) out_idx_f[row] = (float)bi;
    }
}

// ================= classifier GEMM (bf16 HMMA) + bias ========================
__global__ __launch_bounds__(256) void cls_mma_kernel(
    const __nv_bfloat16* __restrict__ A, const __nv_bfloat16* __restrict__ Bm,
    const float* __restrict__ bias, float* __restrict__ C, int N)
{
    extern __shared__ char sm[];
    char* A0 = sm;            char* A1 = sm + TSZ;
    char* B0 = sm + 2 * TSZ;  char* B1 = sm + 3 * TSZ;

    int tid = threadIdx.x, w = tid >> 5, lane = tid & 31;
    int wm = w & 3, wn = w >> 2;
    int g = lane >> 2, tig = lane & 3;
    int bm = blockIdx.y * 128, bn = blockIdx.x * 128;

    float acc[2][8][4];
    #pragma unroll
    for (int m2 = 0; m2 < 2; m2++)
        #pragma unroll
        for (int n = 0; n < 8; n++)
            #pragma unroll
            for (int q = 0; q < 4; q++) acc[m2][n][q] = 0.0f;

    load_tile(A0, A, bm, 0, tid);
    load_tile(B0, Bm, bn, 0, tid);
    __syncthreads();
    for (int c = 0; c < 16; c++) {
        if (c + 1 < 16) {
            char* an = (c & 1) ? A0 : A1;
            char* bn2 = (c & 1) ? B0 : B1;
            load_tile(an, A, bm, (c + 1) * 64, tid);
            load_tile(bn2, Bm, bn, (c + 1) * 64, tid);
        }
        mma_chunk((c & 1) ? A1 : A0, (c & 1) ? B1 : B0, wm, wn, g, tig, acc);
        __syncthreads();
    }

    #pragma unroll
    for (int m2 = 0; m2 < 2; m2++)
        #pragma unroll
        for (int q = 0; q < 4; q++) {
            int row = bm + wm * 32 + m2 * 16 + (q >> 1) * 8 + g;
            #pragma unroll
            for (int n = 0; n < 8; n++) {
                int col = bn + wn * 64 + n * 8 + 2 * tig + (q & 1);
                C[(size_t)row * N + col] = acc[m2][n][q] + __ldg(&bias[col]);
            }
        }
}

// ================= R1-proven fp32 kernels ====================================
__global__ void rowsumsq_kernel(const float* __restrict__ src, float* __restrict__ dst,
                                int rows, int cols)
{
    int row  = blockIdx.x * (blockDim.x >> 5) + (threadIdx.x >> 5);
    int lane = threadIdx.x & 31;
    if (row >= rows) return;
    const float* r = src + (size_t)row * cols;
    double s = 0.0;
    for (int j = lane; j < cols; j += 32) {
        float v = r[j];
        s += (double)v * (double)v;
    }
    #pragma unroll
    for (int o = 16; o > 0; o >>= 1) s += __shfl_down_sync(0xffffffffu, s, o);
    if (lane == 0) dst[row] = (float)s;
}

__global__ __launch_bounds__(256) void sgemm_nt_bias(
    const float* __restrict__ A, const float* __restrict__ Bm,
    const float* __restrict__ bias, float* __restrict__ C,
    int M, int N, int Kd)
{
    const int BK = 8;
    __shared__ float As[BK][128];
    __shared__ float Bs[BK][128];
    int bm = blockIdx.y * 128, bn = blockIdx.x * 128;
    int tid = threadIdx.x;
    int tx = tid & 15, ty = tid >> 4;
    int lrow = tid >> 1, lcol = (tid & 1) * 4;
    const float* Aptr = A  + (size_t)(bm + lrow) * Kd + lcol;
    const float* Bptr = Bm + (size_t)(bn + lrow) * Kd + lcol;
    float acc[8][8];
    #pragma unroll
    for (int i = 0; i < 8; i++)
        #pragma unroll
        for (int j = 0; j < 8; j++) acc[i][j] = 0.0f;
    for (int k0 = 0; k0 < Kd; k0 += BK) {
        float4 av = *(const float4*)(Aptr + k0);
        float4 bv = *(const float4*)(Bptr + k0);
        As[lcol + 0][lrow] = av.x; As[lcol + 1][lrow] = av.y;
        As[lcol + 2][lrow] = av.z; As[lcol + 3][lrow] = av.w;
        Bs[lcol + 0][lrow] = bv.x; Bs[lcol + 1][lrow] = bv.y;
        Bs[lcol + 2][lrow] = bv.z; Bs[lcol + 3][lrow] = bv.w;
        __syncthreads();
        #pragma unroll
        for (int kk = 0; kk < BK; kk++) {
            float ar[8], br[8];
            #pragma unroll
            for (int i = 0; i < 8; i++) ar[i] = As[kk][ty * 8 + i];
            #pragma unroll
            for (int j = 0; j < 8; j++) br[j] = Bs[kk][tx * 8 + j];
            #pragma unroll
            for (int i = 0; i < 8; i++)
                #pragma unroll
                for (int j = 0; j < 8; j++)
                    acc[i][j] = fmaf(ar[i], br[j], acc[i][j]);
        }
        __syncthreads();
    }
    #pragma unroll
    for (int i = 0; i < 8; i++) {
        int r = bm + ty * 8 + i;
        #pragma unroll
        for (int j = 0; j < 8; j += 4) {
            int c = bn + tx * 8 + j;
            float4 o;
            o.x = acc[i][j + 0] + bias[c + 0];
            o.y = acc[i][j + 1] + bias[c + 1];
            o.z = acc[i][j + 2] + bias[c + 2];
            o.w = acc[i][j + 3] + bias[c + 3];
            *(float4*)&C[(size_t)r * N + c] = o;
        }
    }
}

// ================= small kernels =============================================
__global__ void f2bf_kernel(const float* __restrict__ x, __nv_bfloat16* y, size_t n)
{
    size_t i = (size_t)blockIdx.x * blockDim.x + threadIdx.x;
    if (i < n) y[i] = __float2bfloat16(x[i]);
}

__global__ void gather_qb_kernel(const float* __restrict__ cb)
{
    size_t i = (size_t)blockIdx.x * blockDim.x + threadIdx.x;
    int row = (int)(i >> 10);
    int col = (int)(i & 1023);
    g_qb[i] = __float2bfloat16(cb[(size_t)g_idx[row] * L_ + col]);
}

__global__ void loss_kernel(const float* __restrict__ cb)
{
    int row = blockIdx.x;
    const float* ze = g_ze + (size_t)row * L_;
    const float* q  = cb   + (size_t)g_idx[row] * L_;
    double s = 0.0;
    for (int j = threadIdx.x; j < L_; j += blockDim.x) {
        float dlt = q[j] - ze[j];
        s += (double)dlt * (double)dlt;
    }
    __shared__ double sh[256];
    sh[threadIdx.x] = s;
    __syncthreads();
    for (int o = 128; o > 0; o >>= 1) {
        if (threadIdx.x < o) sh[threadIdx.x] += sh[threadIdx.x + o];
        __syncthreads();
    }
    if (threadIdx.x == 0) g_rowloss[row] = sh[0];
}

__global__ void loss_reduce_kernel(float* __restrict__ out_loss)
{
    __shared__ double sh[256];
    double s = 0.0;
    for (int r = threadIdx.x; r < B_; r += 256) s += g_rowloss[r];
    sh[threadIdx.x] = s;
    __syncthreads();
    for (int o = 128; o > 0; o >>= 1) {
        if (threadIdx.x < o) sh[threadIdx.x] += sh[threadIdx.x + o];
        __syncthreads();
    }
    if (threadIdx.x == 0) {
        float m = (float)(sh[0] / ((double)B_ * (double)L_));
        out_loss[0] = m + 0.25f * m;
    }
}

__global__ void softmax_kernel(float* __restrict__ logits)
{
    int row = blockIdx.x;
    float* p = logits + (size_t)row * O_;
    float v = p[threadIdx.x];
    __shared__ float shm[4];
    float m = v;
    #pragma unroll
    for (int o = 16; o > 0; o >>= 1) m = fmaxf(m, __shfl_xor_sync(0xffffffffu, m, o));
    if ((threadIdx.x & 31) == 0) shm[threadIdx.x >> 5] = m;
    __syncthreads();
    float mm = fmaxf(fmaxf(shm[0], shm[1]), fmaxf(shm[2], shm[3]));
    __syncthreads();
    float e = expf(v - mm);
    float s = e;
    #pragma unroll
    for (int o = 16; o > 0; o >>= 1) s += __shfl_xor_sync(0xffffffffu, s, o);
    if ((threadIdx.x & 31) == 0) shm[threadIdx.x >> 5] = s;
    __syncthreads();
    float ss = shm[0] + shm[1] + shm[2] + shm[3];
    p[threadIdx.x] = e / ss;
}

// ================= launch =====================================================
extern "C" void kernel_launch(void* const* d_in, const int* in_sizes, int n_in,
                              void* d_out, int out_size)
{
    const float* x     = (const float*)d_in[0];
    const float* W_enc = (const float*)d_in[1];
    const float* b_enc = (const float*)d_in[2];
    const float* cb    = (const float*)d_in[3];
    const float* W_cls = (const float*)d_in[4];
    const float* b_cls = (const float*)d_in[5];
    float* out = (float*)d_out;

    float* out_logits = out;
    float* out_loss   = out + (size_t)B_ * O_;
    float* out_idx    = out + (size_t)B_ * O_ + 1;
    int has_loss = (out_size >= B_ * O_ + 1);
    int has_idx  = (out_size >= B_ * O_ + 1 + B_);

    cudaFuncSetAttribute(dist_mma_kernel, cudaFuncAttributeMaxDynamicSharedMemorySize, SM_DYN);
    cudaFuncSetAttribute(cls_mma_kernel, cudaFuncAttributeMaxDynamicSharedMemorySize, SM_DYN);

    void *p;
    float *ze, *Pv, *cv;
    __nv_bfloat16 *zeb, *cbb, *qb, *wclsb;
    cudaGetSymbolAddress(&p, g_ze);    ze    = (float*)p;
    cudaGetSymbolAddress(&p, g_P);     Pv    = (float*)p;
    cudaGetSymbolAddress(&p, g_c);     cv    = (float*)p;
    cudaGetSymbolAddress(&p, g_zeb);   zeb   = (__nv_bfloat16*)p;
    cudaGetSymbolAddress(&p, g_cbb);   cbb   = (__nv_bfloat16*)p;
    cudaGetSymbolAddress(&p, g_qb);    qb    = (__nv_bfloat16*)p;
    cudaGetSymbolAddress(&p, g_wclsb); wclsb = (__nv_bfloat16*)p;

    // codebook norms + bf16 conversions
    rowsumsq_kernel<<<K_ / 8, 256>>>(cb, cv, K_, L_);
    f2bf_kernel<<<(unsigned)((size_t)K_ * L_ / 256), 256>>>(cb, cbb, (size_t)K_ * L_);
    f2bf_kernel<<<(unsigned)((size_t)O_ * L_ / 256), 256>>>(W_cls, wclsb, (size_t)O_ * L_);

    // z_e: sequential-k fp32 SGEMM (bit-proven path)
    {
        dim3 grid(L_ / 128, B_ / 128);
        sgemm_nt_bias<<<grid, 256>>>(x, W_enc, b_enc, ze, B_, L_, TD_);
    }
    rowsumsq_kernel<<<B_ / 8, 256>>>(ze, Pv, B_, L_);
    f2bf_kernel<<<(unsigned)((size_t)B_ * L_ / 256), 256>>>(ze, zeb, (size_t)B_ * L_);

    // distances: bf16 HMMA sweep + exact fp32 refine
    dist_mma_kernel<<<B_ / 128, 256, SM_DYN>>>();
    refine_kernel<<<B_ / 8, 256>>>(cb, out_idx, has_idx);

    // loss
    loss_kernel<<<B_, 256>>>(cb);
    if (has_loss) loss_reduce_kernel<<<1, 256>>>(out_loss);

    // classifier on gathered codebook rows (z_q == quantized fwd) + softmax
    gather_qb_kernel<<<(unsigned)((size_t)B_ * L_ / 256), 256>>>(cb);
    {
        dim3 grid(O_ / 128, B_ / 128);
        cls_mma_kernel<<<grid, 256, SM_DYN>>>(qb, wclsb, b_cls, out_logits, O_);
    }
    softmax_kernel<<<B_, 128>>>(out_logits);
}

// round 5
// speedup vs baseline: 25.2734x; 25.2734x over previous
#include <cuda_runtime.h>
#include <cuda_bf16.h>
#include <cstdint>
#include <cfloat>

#define B_  16384
#define TD_ 4096
#define L_  1024
#define K_  8192
#define O_  128

#define MARGIN 1.5e-3f

// ---------------- scratch (device globals) -----------------------------------
__device__ float  g_ze[(size_t)B_ * L_];            // 64 MB
__device__ __nv_bfloat16 g_zeb[(size_t)B_ * L_];    // 32 MB
__device__ __nv_bfloat16 g_cbb[(size_t)K_ * L_];    // 16 MB
__device__ __nv_bfloat16 g_qb[(size_t)B_ * L_];     // 32 MB (gathered codebook rows)
__device__ __nv_bfloat16 g_wclsb[(size_t)O_ * L_];
__device__ float  g_P[B_];
__device__ float  g_c[K_];
__device__ int    g_idx[B_];
__device__ uint32_t g_cand_col[(size_t)B_ * 32];
__device__ float    g_cand_d[(size_t)B_ * 32];
__device__ double g_rowloss[B_];

// ---------------- mma.sync helper (m16n8k16 bf16, fp32 accum) ----------------
__device__ __forceinline__ void mma16816(float* c, uint32_t a0, uint32_t a1,
                                         uint32_t a2, uint32_t a3,
                                         uint32_t b0, uint32_t b1) {
    asm volatile(
        "mma.sync.aligned.m16n8k16.row.col.f32.bf16.bf16.f32 "
        "{%0,%1,%2,%3}, {%4,%5,%6,%7}, {%8,%9}, {%0,%1,%2,%3};"
        : "+f"(c[0]), "+f"(c[1]), "+f"(c[2]), "+f"(c[3])
        : "r"(a0), "r"(a1), "r"(a2), "r"(a3), "r"(b0), "r"(b1));
}

// smem tile: 128 rows x 64 bf16, padded to 72 bf16 (144B) per row.
#define TROW 144
#define TSZ  (128 * TROW)      // 18432 B per stage
#define SM_DYN (4 * TSZ + 512)

__device__ __forceinline__ void load_tile(char* dst, const __nv_bfloat16* src,
                                          int row0, int kc, int tid) {
    int r = tid >> 1, seg = tid & 1;
    const uint4* s = (const uint4*)(src + (size_t)(row0 + r) * L_ + kc + seg * 32);
    uint4* d = (uint4*)(dst + r * TROW + seg * 64);
    d[0] = s[0]; d[1] = s[1]; d[2] = s[2]; d[3] = s[3];
}

__device__ __forceinline__ void mma_chunk(const char* smA, const char* smB,
                                          int wm, int wn, int g, int tig,
                                          float acc[2][8][4]) {
    #pragma unroll
    for (int kk = 0; kk < 4; kk++) {
        uint32_t a[2][4];
        #pragma unroll
        for (int m2 = 0; m2 < 2; m2++) {
            int r0 = wm * 32 + m2 * 16 + g;
            int cb0 = (kk * 16 + 2 * tig) * 2;
            a[m2][0] = *(const uint32_t*)(smA + r0 * TROW + cb0);
            a[m2][1] = *(const uint32_t*)(smA + (r0 + 8) * TROW + cb0);
            a[m2][2] = *(const uint32_t*)(smA + r0 * TROW + cb0 + 16);
            a[m2][3] = *(const uint32_t*)(smA + (r0 + 8) * TROW + cb0 + 16);
        }
        #pragma unroll
        for (int n = 0; n < 8; n++) {
            int cn = wn * 64 + n * 8 + g;
            int cb0 = (kk * 16 + 2 * tig) * 2;
            uint32_t b0 = *(const uint32_t*)(smB + cn * TROW + cb0);
            uint32_t b1 = *(const uint32_t*)(smB + cn * TROW + cb0 + 16);
            mma16816(acc[0][n], a[0][0], a[0][1], a[0][2], a[0][3], b0, b1);
            mma16816(acc[1][n], a[1][0], a[1][1], a[1][2], a[1][3], b0, b1);
        }
    }
}

// ================= fused dist GEMM (bf16 HMMA) + per-thread top-4 ============
__global__ __launch_bounds__(256) void dist_mma_kernel(void)
{
    extern __shared__ char sm[];
    char* A0 = sm;            char* A1 = sm + TSZ;
    char* B0 = sm + 2 * TSZ;  char* B1 = sm + 3 * TSZ;
    float* sc = (float*)(sm + 4 * TSZ);

    int tid = threadIdx.x, w = tid >> 5, lane = tid & 31;
    int wm = w & 3, wn = w >> 2;
    int g = lane >> 2, tig = lane & 3;
    int bm = blockIdx.x * 128;

    float P4[4];
    #pragma unroll
    for (int ri = 0; ri < 4; ri++) P4[ri] = g_P[bm + wm * 32 + ri * 8 + g];

    // per (thread,row) sorted top-4: v0 <= v1 <= v2 <= v3 (registers only)
    float v0[4], v1[4], v2[4], v3[4];
    uint32_t i0[4], i1[4], i2[4], i3[4];
    #pragma unroll
    for (int ri = 0; ri < 4; ri++) {
        v0[ri] = v1[ri] = v2[ri] = v3[ri] = FLT_MAX;
        i0[ri] = i1[ri] = i2[ri] = i3[ri] = 0xFFFFFFFFu;
    }

    for (int nt = 0; nt < K_ / 128; nt++) {
        int n0 = nt * 128;
        if (tid < 128) sc[tid] = g_c[n0 + tid];

        float acc[2][8][4];
        #pragma unroll
        for (int m2 = 0; m2 < 2; m2++)
            #pragma unroll
            for (int n = 0; n < 8; n++)
                #pragma unroll
                for (int q = 0; q < 4; q++) acc[m2][n][q] = 0.0f;

        load_tile(A0, g_zeb, bm, 0, tid);
        load_tile(B0, g_cbb, n0, 0, tid);
        __syncthreads();
        for (int c = 0; c < 16; c++) {
            if (c + 1 < 16) {
                char* an = (c & 1) ? A0 : A1;
                char* bn2 = (c & 1) ? B0 : B1;
                load_tile(an, g_zeb, bm, (c + 1) * 64, tid);
                load_tile(bn2, g_cbb, n0, (c + 1) * 64, tid);
            }
            mma_chunk((c & 1) ? A1 : A0, (c & 1) ? B1 : B0, wm, wn, g, tig, acc);
            __syncthreads();
        }

        // epilogue: sorted-insert into top-4 (strict <, ascending col order
        // => first-index-first among exact ties)
        #pragma unroll
        for (int m2 = 0; m2 < 2; m2++) {
            #pragma unroll
            for (int q = 0; q < 4; q++) {
                int ri = m2 * 2 + (q >> 1);
                float P = P4[ri];
                #pragma unroll
                for (int n = 0; n < 8; n++) {
                    int cl = wn * 64 + n * 8 + 2 * tig + (q & 1);
                    float t = P - 2.0f * acc[m2][n][q];
                    float d = t + sc[cl];
                    uint32_t col = (uint32_t)(n0 + cl);
                    if (d < v3[ri]) {
                        if (d < v2[ri]) {
                            v3[ri] = v2[ri]; i3[ri] = i2[ri];
                            if (d < v1[ri]) {
                                v2[ri] = v1[ri]; i2[ri] = i1[ri];
                                if (d < v0[ri]) {
                                    v1[ri] = v0[ri]; i1[ri] = i0[ri];
                                    v0[ri] = d; i0[ri] = col;
                                } else { v1[ri] = d; i1[ri] = col; }
                            } else { v2[ri] = d; i2[ri] = col; }
                        } else { v3[ri] = d; i3[ri] = col; }
                    }
                }
            }
        }
        __syncthreads();
    }

    // write top-4 per (thread,row): slot = tig*2 + wn
    int slot = tig * 2 + wn;
    #pragma unroll
    for (int ri = 0; ri < 4; ri++) {
        int row = bm + wm * 32 + ri * 8 + g;
        size_t base = (size_t)row * 32 + slot * 4;
        g_cand_col[base + 0] = i0[ri];  g_cand_d[base + 0] = v0[ri];
        g_cand_col[base + 1] = i1[ri];  g_cand_d[base + 1] = v1[ri];
        g_cand_col[base + 2] = i2[ri];  g_cand_d[base + 2] = v2[ri];
        g_cand_col[base + 3] = i3[ri];  g_cand_d[base + 3] = v3[ri];
    }
}

// ================= exact refinement (sequential-k fp32 fma chain) ============
__global__ void refine_kernel(const float* __restrict__ cb,
                              float* __restrict__ out_idx_f, int write_idx)
{
    int w = threadIdx.x >> 5, lane = threadIdx.x & 31;
    int row = blockIdx.x * 8 + w;
    const float* ze = g_ze + (size_t)row * L_;
    float P = g_P[row];

    uint32_t ecol = g_cand_col[(size_t)row * 32 + lane];
    float ed = g_cand_d[(size_t)row * 32 + lane];
    int eslot = lane & 3;   // entry index within its thread's sorted top-4

    // global approx min over the 32 entries
    float m = ed;
    #pragma unroll
    for (int o = 16; o > 0; o >>= 1)
        m = fminf(m, __shfl_xor_sync(0xffffffffu, m, o));

    // capture guarantee: if any source thread's 4th-smallest lies inside the
    // margin band, its top-4 may have dropped a needed candidate -> full scan
    int ovf = __any_sync(0xffffffffu, (eslot == 3) && (ed < m + MARGIN));

    float bd = FLT_MAX; int bi = 0x7FFFFFFF;
    if (!ovf) {
        if (ecol != 0xFFFFFFFFu && ed < m + MARGIN) {
            const float* e = cb + (size_t)ecol * L_;
            float s = 0.0f;
            #pragma unroll 4
            for (int k = 0; k < L_; k++) s = fmaf(__ldg(&ze[k]), __ldg(&e[k]), s);
            float t = P - 2.0f * s;
            bd = t + __ldg(&g_c[ecol]);
            bi = (int)ecol;
        }
    } else {
        for (int col = lane; col < K_; col += 32) {
            const float* e = cb + (size_t)col * L_;
            float s = 0.0f;
            #pragma unroll 4
            for (int k = 0; k < L_; k++) s = fmaf(__ldg(&ze[k]), __ldg(&e[k]), s);
            float t = P - 2.0f * s;
            float d = t + __ldg(&g_c[col]);
            if (d < bd || (d == bd && col < bi)) { bd = d; bi = col; }
        }
    }
    #pragma unroll
    for (int o = 16; o > 0; o >>= 1) {
        float od = __shfl_xor_sync(0xffffffffu, bd, o);
        int oi = __shfl_xor_sync(0xffffffffu, bi, o);
        if (od < bd || (od == bd && oi < bi)) { bd = od; bi = oi; }
    }
    if (lane == 0) {
        g_idx[row] = bi;
        if (write_idx) out_idx_f[row] = (float)bi;
    }
}

// ================= classifier GEMM (bf16 HMMA) + bias ========================
__global__ __launch_bounds__(256) void cls_mma_kernel(
    const __nv_bfloat16* __restrict__ A, const __nv_bfloat16* __restrict__ Bm,
    const float* __restrict__ bias, float* __restrict__ C, int N)
{
    extern __shared__ char sm[];
    char* A0 = sm;            char* A1 = sm + TSZ;
    char* B0 = sm + 2 * TSZ;  char* B1 = sm + 3 * TSZ;

    int tid = threadIdx.x, w = tid >> 5, lane = tid & 31;
    int wm = w & 3, wn = w >> 2;
    int g = lane >> 2, tig = lane & 3;
    int bm = blockIdx.y * 128, bn = blockIdx.x * 128;

    float acc[2][8][4];
    #pragma unroll
    for (int m2 = 0; m2 < 2; m2++)
        #pragma unroll
        for (int n = 0; n < 8; n++)
            #pragma unroll
            for (int q = 0; q < 4; q++) acc[m2][n][q] = 0.0f;

    load_tile(A0, A, bm, 0, tid);
    load_tile(B0, Bm, bn, 0, tid);
    __syncthreads();
    for (int c = 0; c < 16; c++) {
        if (c + 1 < 16) {
            char* an = (c & 1) ? A0 : A1;
            char* bn2 = (c & 1) ? B0 : B1;
            load_tile(an, A, bm, (c + 1) * 64, tid);
            load_tile(bn2, Bm, bn, (c + 1) * 64, tid);
        }
        mma_chunk((c & 1) ? A1 : A0, (c & 1) ? B1 : B0, wm, wn, g, tig, acc);
        __syncthreads();
    }

    #pragma unroll
    for (int m2 = 0; m2 < 2; m2++)
        #pragma unroll
        for (int q = 0; q < 4; q++) {
            int row = bm + wm * 32 + m2 * 16 + (q >> 1) * 8 + g;
            #pragma unroll
            for (int n = 0; n < 8; n++) {
                int col = bn + wn * 64 + n * 8 + 2 * tig + (q & 1);
                C[(size_t)row * N + col] = acc[m2][n][q] + __ldg(&bias[col]);
            }
        }
}

// ================= R1-proven fp32 kernels ====================================
__global__ void rowsumsq_kernel(const float* __restrict__ src, float* __restrict__ dst,
                                int rows, int cols)
{
    int row  = blockIdx.x * (blockDim.x >> 5) + (threadIdx.x >> 5);
    int lane = threadIdx.x & 31;
    if (row >= rows) return;
    const float* r = src + (size_t)row * cols;
    double s = 0.0;
    for (int j = lane; j < cols; j += 32) {
        float v = r[j];
        s += (double)v * (double)v;
    }
    #pragma unroll
    for (int o = 16; o > 0; o >>= 1) s += __shfl_down_sync(0xffffffffu, s, o);
    if (lane == 0) dst[row] = (float)s;
}

__global__ __launch_bounds__(256) void sgemm_nt_bias(
    const float* __restrict__ A, const float* __restrict__ Bm,
    const float* __restrict__ bias, float* __restrict__ C,
    int M, int N, int Kd)
{
    const int BK = 8;
    __shared__ float As[BK][128];
    __shared__ float Bs[BK][128];
    int bm = blockIdx.y * 128, bn = blockIdx.x * 128;
    int tid = threadIdx.x;
    int tx = tid & 15, ty = tid >> 4;
    int lrow = tid >> 1, lcol = (tid & 1) * 4;
    const float* Aptr = A  + (size_t)(bm + lrow) * Kd + lcol;
    const float* Bptr = Bm + (size_t)(bn + lrow) * Kd + lcol;
    float acc[8][8];
    #pragma unroll
    for (int i = 0; i < 8; i++)
        #pragma unroll
        for (int j = 0; j < 8; j++) acc[i][j] = 0.0f;
    for (int k0 = 0; k0 < Kd; k0 += BK) {
        float4 av = *(const float4*)(Aptr + k0);
        float4 bv = *(const float4*)(Bptr + k0);
        As[lcol + 0][lrow] = av.x; As[lcol + 1][lrow] = av.y;
        As[lcol + 2][lrow] = av.z; As[lcol + 3][lrow] = av.w;
        Bs[lcol + 0][lrow] = bv.x; Bs[lcol + 1][lrow] = bv.y;
        Bs[lcol + 2][lrow] = bv.z; Bs[lcol + 3][lrow] = bv.w;
        __syncthreads();
        #pragma unroll
        for (int kk = 0; kk < BK; kk++) {
            float ar[8], br[8];
            #pragma unroll
            for (int i = 0; i < 8; i++) ar[i] = As[kk][ty * 8 + i];
            #pragma unroll
            for (int j = 0; j < 8; j++) br[j] = Bs[kk][tx * 8 + j];
            #pragma unroll
            for (int i = 0; i < 8; i++)
                #pragma unroll
                for (int j = 0; j < 8; j++)
                    acc[i][j] = fmaf(ar[i], br[j], acc[i][j]);
        }
        __syncthreads();
    }
    #pragma unroll
    for (int i = 0; i < 8; i++) {
        int r = bm + ty * 8 + i;
        #pragma unroll
        for (int j = 0; j < 8; j += 4) {
            int c = bn + tx * 8 + j;
            float4 o;
            o.x = acc[i][j + 0] + bias[c + 0];
            o.y = acc[i][j + 1] + bias[c + 1];
            o.z = acc[i][j + 2] + bias[c + 2];
            o.w = acc[i][j + 3] + bias[c + 3];
            *(float4*)&C[(size_t)r * N + c] = o;
        }
    }
}

// ================= small kernels =============================================
__global__ void f2bf_kernel(const float* __restrict__ x, __nv_bfloat16* y, size_t n)
{
    size_t i = (size_t)blockIdx.x * blockDim.x + threadIdx.x;
    if (i < n) y[i] = __float2bfloat16(x[i]);
}

__global__ void gather_qb_kernel(const float* __restrict__ cb)
{
    size_t i = (size_t)blockIdx.x * blockDim.x + threadIdx.x;
    int row = (int)(i >> 10);
    int col = (int)(i & 1023);
    g_qb[i] = __float2bfloat16(cb[(size_t)g_idx[row] * L_ + col]);
}

__global__ void loss_kernel(const float* __restrict__ cb)
{
    int row = blockIdx.x;
    const float* ze = g_ze + (size_t)row * L_;
    const float* q  = cb   + (size_t)g_idx[row] * L_;
    double s = 0.0;
    for (int j = threadIdx.x; j < L_; j += blockDim.x) {
        float dlt = q[j] - ze[j];
        s += (double)dlt * (double)dlt;
    }
    __shared__ double sh[256];
    sh[threadIdx.x] = s;
    __syncthreads();
    for (int o = 128; o > 0; o >>= 1) {
        if (threadIdx.x < o) sh[threadIdx.x] += sh[threadIdx.x + o];
        __syncthreads();
    }
    if (threadIdx.x == 0) g_rowloss[row] = sh[0];
}

__global__ void loss_reduce_kernel(float* __restrict__ out_loss)
{
    __shared__ double sh[256];
    double s = 0.0;
    for (int r = threadIdx.x; r < B_; r += 256) s += g_rowloss[r];
    sh[threadIdx.x] = s;
    __syncthreads();
    for (int o = 128; o > 0; o >>= 1) {
        if (threadIdx.x < o) sh[threadIdx.x] += sh[threadIdx.x + o];
        __syncthreads();
    }
    if (threadIdx.x == 0) {
        float m = (float)(sh[0] / ((double)B_ * (double)L_));
        out_loss[0] = m + 0.25f * m;
    }
}

__global__ void softmax_kernel(float* __restrict__ logits)
{
    int row = blockIdx.x;
    float* p = logits + (size_t)row * O_;
    float v = p[threadIdx.x];
    __shared__ float shm[4];
    float m = v;
    #pragma unroll
    for (int o = 16; o > 0; o >>= 1) m = fmaxf(m, __shfl_xor_sync(0xffffffffu, m, o));
    if ((threadIdx.x & 31) == 0) shm[threadIdx.x >> 5] = m;
    __syncthreads();
    float mm = fmaxf(fmaxf(shm[0], shm[1]), fmaxf(shm[2], shm[3]));
    __syncthreads();
    float e = expf(v - mm);
    float s = e;
    #pragma unroll
    for (int o = 16; o > 0; o >>= 1) s += __shfl_xor_sync(0xffffffffu, s, o);
    if ((threadIdx.x & 31) == 0) shm[threadIdx.x >> 5] = s;
    __syncthreads();
    float ss = shm[0] + shm[1] + shm[2] + shm[3];
    p[threadIdx.x] = e / ss;
}

// ================= launch =====================================================
extern "C" void kernel_launch(void* const* d_in, const int* in_sizes, int n_in,
                              void* d_out, int out_size)
{
    const float* x     = (const float*)d_in[0];
    const float* W_enc = (const float*)d_in[1];
    const float* b_enc = (const float*)d_in[2];
    const float* cb    = (const float*)d_in[3];
    const float* W_cls = (const float*)d_in[4];
    const float* b_cls = (const float*)d_in[5];
    float* out = (float*)d_out;

    float* out_logits = out;
    float* out_loss   = out + (size_t)B_ * O_;
    float* out_idx    = out + (size_t)B_ * O_ + 1;
    int has_loss = (out_size >= B_ * O_ + 1);
    int has_idx  = (out_size >= B_ * O_ + 1 + B_);

    cudaFuncSetAttribute(dist_mma_kernel, cudaFuncAttributeMaxDynamicSharedMemorySize, SM_DYN);
    cudaFuncSetAttribute(cls_mma_kernel, cudaFuncAttributeMaxDynamicSharedMemorySize, SM_DYN);

    void *p;
    float *ze, *Pv, *cv;
    __nv_bfloat16 *zeb, *cbb, *qb, *wclsb;
    cudaGetSymbolAddress(&p, g_ze);    ze    = (float*)p;
    cudaGetSymbolAddress(&p, g_P);     Pv    = (float*)p;
    cudaGetSymbolAddress(&p, g_c);     cv    = (float*)p;
    cudaGetSymbolAddress(&p, g_zeb);   zeb   = (__nv_bfloat16*)p;
    cudaGetSymbolAddress(&p, g_cbb);   cbb   = (__nv_bfloat16*)p;
    cudaGetSymbolAddress(&p, g_qb);    qb    = (__nv_bfloat16*)p;
    cudaGetSymbolAddress(&p, g_wclsb); wclsb = (__nv_bfloat16*)p;

    // codebook norms + bf16 conversions
    rowsumsq_kernel<<<K_ / 8, 256>>>(cb, cv, K_, L_);
    f2bf_kernel<<<(unsigned)((size_t)K_ * L_ / 256), 256>>>(cb, cbb, (size_t)K_ * L_);
    f2bf_kernel<<<(unsigned)((size_t)O_ * L_ / 256), 256>>>(W_cls, wclsb, (size_t)O_ * L_);

    // z_e: sequential-k fp32 SGEMM (bit-proven path)
    {
        dim3 grid(L_ / 128, B_ / 128);
        sgemm_nt_bias<<<grid, 256>>>(x, W_enc, b_enc, ze, B_, L_, TD_);
    }
    rowsumsq_kernel<<<B_ / 8, 256>>>(ze, Pv, B_, L_);
    f2bf_kernel<<<(unsigned)((size_t)B_ * L_ / 256), 256>>>(ze, zeb, (size_t)B_ * L_);

    // distances: bf16 HMMA sweep (top-4/thread) + exact fp32 refine
    dist_mma_kernel<<<B_ / 128, 256, SM_DYN>>>();
    refine_kernel<<<B_ / 8, 256>>>(cb, out_idx, has_idx);

    // loss
    loss_kernel<<<B_, 256>>>(cb);
    if (has_loss) loss_reduce_kernel<<<1, 256>>>(out_loss);

    // classifier on gathered codebook rows (z_q == quantized fwd) + softmax
    gather_qb_kernel<<<(unsigned)((size_t)B_ * L_ / 256), 256>>>(cb);
    {
        dim3 grid(O_ / 128, B_ / 128);
        cls_mma_kernel<<<grid, 256, SM_DYN>>>(qb, wclsb, b_cls, out_logits, O_);
    }
    softmax_kernel<<<B_, 128>>>(out_logits);
}